// round 15
// baseline (speedup 1.0000x reference)
#include <cuda_runtime.h>
#include <cuda_bf16.h>
#include <cstdint>

#define BB    256
#define TT    512
#define FF    64
#define UU    256
#define G4    1024
#define KC    320
#define OUTS  64
#define OD    8
#define MTOT  (BB*TT)   // 131072

// ======================= device scratch =======================
__device__ __nv_bfloat16 g_xc_hi[(size_t)MTOT * KC];
__device__ __nv_bfloat16 g_xc_lo[(size_t)MTOT * KC];
__device__ __nv_bfloat16 g_a_hi [(size_t)MTOT * UU];
__device__ __nv_bfloat16 g_a_lo [(size_t)MTOT * UU];
__device__ __nv_bfloat16 g_wt_hi[G4 * UU];
__device__ __nv_bfloat16 g_wt_lo[G4 * UU];
__device__ __nv_bfloat16 g_ut_hi[G4 * UU];
__device__ __nv_bfloat16 g_ut_lo[G4 * UU];
__device__ __nv_bfloat16 g_cwt_hi[UU * KC];
__device__ __nv_bfloat16 g_cwt_lo[UU * KC];
__device__ float g_xw  [(size_t)MTOT * G4];
__device__ float g_hfin[BB * UU];
__device__ float g_cfin[BB * UU];
__device__ float g_hdec[(size_t)BB * OUTS * UU];
__device__ float g_wc  [UU * G4];

// ======================= PTX helpers (base-target only) =======================
__device__ __forceinline__ uint32_t smem_u32(const void* p) {
    uint32_t a;
    asm("{ .reg .u64 t; cvta.to.shared.u64 t, %1; cvt.u32.u64 %0, t; }" : "=r"(a) : "l"(p));
    return a;
}
__device__ __forceinline__ void ldm_x4(uint32_t* r, uint32_t addr) {
    asm volatile("ldmatrix.sync.aligned.m8n8.x4.shared.b16 {%0,%1,%2,%3}, [%4];"
        : "=r"(r[0]), "=r"(r[1]), "=r"(r[2]), "=r"(r[3]) : "r"(addr));
}
__device__ __forceinline__ void mma16816(float* d, const uint32_t* a, const uint32_t* b) {
    asm volatile("mma.sync.aligned.m16n8k16.row.col.f32.bf16.bf16.f32 "
        "{%0,%1,%2,%3}, {%4,%5,%6,%7}, {%8,%9}, {%0,%1,%2,%3};"
        : "+f"(d[0]), "+f"(d[1]), "+f"(d[2]), "+f"(d[3])
        : "r"(a[0]), "r"(a[1]), "r"(a[2]), "r"(a[3]), "r"(b[0]), "r"(b[1]));
}
__device__ __forceinline__ uint32_t mapa_u32(uint32_t local, uint32_t rank) {
    uint32_t r;
    asm("mapa.shared::cluster.u32 %0, %1, %2;" : "=r"(r) : "r"(local), "r"(rank));
    return r;
}
__device__ __forceinline__ void st_cluster_u16(uint32_t addr, unsigned short v) {
    asm volatile("st.shared::cluster.u16 [%0], %1;" :: "r"(addr), "h"(v) : "memory");
}
__device__ __forceinline__ void mbar_init(uint32_t mb, uint32_t cnt) {
    asm volatile("mbarrier.init.shared.b64 [%0], %1;" :: "r"(mb), "r"(cnt) : "memory");
}
__device__ __forceinline__ void mbar_arrive_remote(uint32_t local_mb, uint32_t rank) {
    uint32_t ra = mapa_u32(local_mb, rank);
    asm volatile("mbarrier.arrive.release.cluster.shared::cluster.b64 _, [%0];"
                 :: "r"(ra) : "memory");
}
__device__ __forceinline__ void mbar_wait(uint32_t mb, uint32_t parity) {
    uint32_t done;
    asm volatile("{\n\t.reg .pred p;\n\t"
        "mbarrier.try_wait.parity.acquire.cluster.shared::cta.b64 p, [%1], %2;\n\t"
        "selp.b32 %0, 1, 0, p;\n\t}" : "=r"(done) : "r"(mb), "r"(parity) : "memory");
    if (!done) {
        asm volatile("{\n\t.reg .pred P1;\n\t"
            "WL_%=:\n\t"
            "mbarrier.try_wait.parity.acquire.cluster.shared::cta.b64 P1, [%0], %1, 0x989680;\n\t"
            "@P1 bra.uni WD_%=;\n\t"
            "bra.uni WL_%=;\n\t"
            "WD_%=:\n\t}" :: "r"(mb), "r"(parity) : "memory");
    }
}
#define CLUSTER_SYNC() do {                                         \
    asm volatile("barrier.cluster.arrive.aligned;" ::: "memory");   \
    asm volatile("barrier.cluster.wait.aligned;" ::: "memory");     \
} while (0)

// ======================= misc helpers =======================
__device__ __forceinline__ float sigm_f(float x) {
    return __fdividef(1.0f, 1.0f + __expf(-x));
}
__device__ __forceinline__ float tanh_f(float x) {
    float xc = fminf(fmaxf(x, -15.0f), 15.0f);
    float e  = __expf(-2.0f * xc);
    return __fdividef(1.0f - e, 1.0f + e);
}
__device__ __forceinline__ void split_bf16(float v, __nv_bfloat16& h, __nv_bfloat16& l) {
    h = __float2bfloat16(v);
    l = __float2bfloat16(v - __bfloat162float(h));
}

// ======================= im2col + split =======================
__global__ void im2col_split(const float* __restrict__ x) {
    size_t idx = (size_t)blockIdx.x * 256 + threadIdx.x;
    int col = (int)(idx % KC);
    size_t mt = idx / KC;
    int t = (int)(mt % TT);
    int b = (int)(mt / TT);
    int k = col >> 6, f = col & 63;
    int tt = t + k - 2;
    float v = (tt >= 0 && tt < TT) ? x[((size_t)b * TT + tt) * FF + f] : 0.0f;
    __nv_bfloat16 h, l; split_bf16(v, h, l);
    g_xc_hi[idx] = h; g_xc_lo[idx] = l;
}

// W[K,N] -> Wt_hi/lo[N,K] bf16 (transpose + split)
__global__ void wsplit(const float* __restrict__ W, __nv_bfloat16* __restrict__ hi,
                       __nv_bfloat16* __restrict__ lo, int K, int N) {
    int idx = blockIdx.x * 256 + threadIdx.x;
    if (idx >= K * N) return;
    int n = idx / K, k = idx % K;
    float v = W[(size_t)k * N + n];
    __nv_bfloat16 h, l; split_bf16(v, h, l);
    hi[idx] = h; lo[idx] = l;
}

// ======================= HMMA split-bf16 GEMM =======================
#define LDP 72
#define TILE_ELE (128 * LDP)

template<int RELU, int OUTMODE>
__global__ __launch_bounds__(256)
void mma_gemm(const __nv_bfloat16* __restrict__ Ahi, const __nv_bfloat16* __restrict__ Alo,
              const __nv_bfloat16* __restrict__ Bhi, const __nv_bfloat16* __restrict__ Blo,
              const float* __restrict__ bias,
              float* __restrict__ C,
              __nv_bfloat16* __restrict__ Chi, __nv_bfloat16* __restrict__ Clo,
              int M, int N, int K)
{
    extern __shared__ __nv_bfloat16 smem[];
    __nv_bfloat16* As_h = smem;
    __nv_bfloat16* As_l = smem + TILE_ELE;
    __nv_bfloat16* Bs_h = smem + 2 * TILE_ELE;
    __nv_bfloat16* Bs_l = smem + 3 * TILE_ELE;

    const int tid  = threadIdx.x;
    const int lane = tid & 31;
    const int wid  = tid >> 5;
    const int wm   = wid & 3;
    const int wn   = wid >> 2;
    const int n0 = blockIdx.x * 128;
    const int m0 = blockIdx.y * 128;

    float acc[2][8][4];
#pragma unroll
    for (int i = 0; i < 2; i++)
#pragma unroll
        for (int j = 0; j < 8; j++)
#pragma unroll
            for (int q = 0; q < 4; q++) acc[i][j][q] = 0.0f;

    const int ar = lane & 15, ac = (lane >> 4) << 3;
    const int br = (lane & 7) + ((lane >> 4) << 3);
    const int bc = ((lane >> 3) & 1) << 3;
    const uint32_t sA_h = smem_u32(As_h), sA_l = smem_u32(As_l);
    const uint32_t sB_h = smem_u32(Bs_h), sB_l = smem_u32(Bs_l);

    for (int k0 = 0; k0 < K; k0 += 64) {
#pragma unroll
        for (int r = 0; r < 4; r++) {
            int unit = tid + r * 256;
            int row = unit >> 3, c8 = (unit & 7) << 3;
            size_t ga = (size_t)(m0 + row) * K + k0 + c8;
            size_t gb = (size_t)(n0 + row) * K + k0 + c8;
            *(uint4*)&As_h[row * LDP + c8] = *(const uint4*)&Ahi[ga];
            *(uint4*)&As_l[row * LDP + c8] = *(const uint4*)&Alo[ga];
            *(uint4*)&Bs_h[row * LDP + c8] = *(const uint4*)&Bhi[gb];
            *(uint4*)&Bs_l[row * LDP + c8] = *(const uint4*)&Blo[gb];
        }
        __syncthreads();

#pragma unroll
        for (int kk = 0; kk < 4; kk++) {
            const int kof = kk * 16;
            uint32_t ah[2][4], al[2][4];
#pragma unroll
            for (int mf = 0; mf < 2; mf++) {
                uint32_t off = (uint32_t)((wm * 32 + mf * 16 + ar) * LDP + kof + ac) * 2;
                ldm_x4(ah[mf], sA_h + off);
                ldm_x4(al[mf], sA_l + off);
            }
#pragma unroll
            for (int g = 0; g < 4; g++) {
                uint32_t bh[4], bl[4];
                uint32_t off = (uint32_t)((wn * 64 + g * 16 + br) * LDP + kof + bc) * 2;
                ldm_x4(bh, sB_h + off);
                ldm_x4(bl, sB_l + off);
#pragma unroll
                for (int mf = 0; mf < 2; mf++) {
                    mma16816(acc[mf][2 * g],     ah[mf], bh);
                    mma16816(acc[mf][2 * g + 1], ah[mf], bh + 2);
                    mma16816(acc[mf][2 * g],     ah[mf], bl);
                    mma16816(acc[mf][2 * g + 1], ah[mf], bl + 2);
                    mma16816(acc[mf][2 * g],     al[mf], bh);
                    mma16816(acc[mf][2 * g + 1], al[mf], bh + 2);
                }
            }
        }
        __syncthreads();
    }

    const int row_base = m0 + wm * 32 + (lane >> 2);
    const int col_loc  = (lane & 3) * 2;
#pragma unroll
    for (int mf = 0; mf < 2; mf++) {
#pragma unroll
        for (int nf = 0; nf < 8; nf++) {
            int c = n0 + wn * 64 + nf * 8 + col_loc;
            float2 bv = *(const float2*)&bias[c];
            int r0 = row_base + mf * 16;
            int r1 = r0 + 8;
            float v00 = acc[mf][nf][0] + bv.x;
            float v01 = acc[mf][nf][1] + bv.y;
            float v10 = acc[mf][nf][2] + bv.x;
            float v11 = acc[mf][nf][3] + bv.y;
            if (RELU) {
                v00 = fmaxf(v00, 0.f); v01 = fmaxf(v01, 0.f);
                v10 = fmaxf(v10, 0.f); v11 = fmaxf(v11, 0.f);
            }
            if (OUTMODE == 0) {
                *(float2*)&C[(size_t)r0 * N + c] = make_float2(v00, v01);
                *(float2*)&C[(size_t)r1 * N + c] = make_float2(v10, v11);
            } else {
                __nv_bfloat16 h0, l0, h1, l1;
                split_bf16(v00, h0, l0); split_bf16(v01, h1, l1);
                *(__nv_bfloat162*)&Chi[(size_t)r0 * N + c] = __nv_bfloat162(h0, h1);
                *(__nv_bfloat162*)&Clo[(size_t)r0 * N + c] = __nv_bfloat162(l0, l1);
                split_bf16(v10, h0, l0); split_bf16(v11, h1, l1);
                *(__nv_bfloat162*)&Chi[(size_t)r1 * N + c] = __nv_bfloat162(h0, h1);
                *(__nv_bfloat162*)&Clo[(size_t)r1 * N + c] = __nv_bfloat162(l0, l1);
            }
        }
    }
}

// ======================= persistent HMMA LSTM scan (DSMEM exchange) ==========
// grid (16,8), cluster (1,8): b-group = 8-CTA cluster; blockIdx.y = u-tile
// (rank). 512 threads = 16 warps (R11 MMA structure). h is exchanged by
// PUSHING each cell's split-bf16 value into all 8 peer CTAs' smem staging
// buffers via mapa + st.shared::cluster (double-buffered), synchronized with
// two mbarriers (8 arrivals; arrive.release.cluster after __syncthreads,
// try_wait.parity.acquire.cluster before MMA). No global h traffic, no
// atomic barrier, no cluster.sync in the loop (R12: cluster.sync flushes L1).
#define HSS 264
#define HBUF (16 * HSS)

__global__ __launch_bounds__(512, 1) __cluster_dims__(1, 8, 1)
void lstm_scan_mma(const float* __restrict__ xw, const float* __restrict__ bias,
                   const __nv_bfloat16* __restrict__ Uth,
                   const __nv_bfloat16* __restrict__ Utl,
                   __nv_bfloat16* __restrict__ yhi, __nv_bfloat16* __restrict__ ylo,
                   float* __restrict__ yfp,
                   int Tlen, int initFromState, int outMode)
{
    __shared__ __nv_bfloat16 hs_h[2 * HBUF];
    __shared__ __nv_bfloat16 hs_l[2 * HBUF];
    __shared__ float z_s[16 * 130];
    __shared__ uint64_t mbar[2];

    const int tid = threadIdx.x, lane = tid & 31, wid = tid >> 5;
    const int b0 = blockIdx.x * 16, u0 = blockIdx.y * 32;

    // ---- register-resident B fragments (m16n8k16 row.col B layout) ----
    const int gate = wid >> 2;
    const int jB = gate * UU + u0 + ((wid & 3) << 3) + (lane >> 2);
    const __nv_bfloat16* uhp = Uth + (size_t)jB * UU;
    const __nv_bfloat16* ulp = Utl + (size_t)jB * UU;
    uint32_t bh[16][2], bl[16][2];
    const int kq = (lane & 3) << 1;
#pragma unroll
    for (int kc = 0; kc < 16; kc++) {
        bh[kc][0] = *(const uint32_t*)&uhp[kc * 16 + kq];
        bh[kc][1] = *(const uint32_t*)&uhp[kc * 16 + kq + 8];
        bl[kc][0] = *(const uint32_t*)&ulp[kc * 16 + kq];
        bl[kc][1] = *(const uint32_t*)&ulp[kc * 16 + kq + 8];
    }

    // ---- per-thread state (one (b,u) cell), coalesced mapping ----
    const int b_l = tid >> 5, u_l = tid & 31;
    const int gidx = (b0 + b_l) * UU + (u0 + u_l);
    float c_reg = initFromState ? g_cfin[gidx] : 0.0f;

    // decoder-mode bias (encoder xw already includes bias)
    float bi = 0.f, bf = 0.f, bg = 0.f, bo = 0.f;
    if (!xw) {
        bi = bias[u0 + u_l];        bf = bias[256 + u0 + u_l];
        bg = bias[512 + u0 + u_l];  bo = bias[768 + u0 + u_l];
    }

    const uint32_t sh_h = smem_u32(hs_h);
    const uint32_t sh_l = smem_u32(hs_l);
    const uint32_t smb  = smem_u32(mbar);
    const uint32_t aoff = (uint32_t)((lane & 15) * HSS + ((lane >> 4) << 3)) * 2;

    // ---- init: mbarriers + local fill of buffer 0 with full h_0 ----
    if (tid == 0) { mbar_init(smb, 8u); mbar_init(smb + 8, 8u); }
#pragma unroll
    for (int it = 0; it < 8; it++) {
        int i = tid + it * 512;              // 4096 cells
        int row = i >> 8, col = i & 255;
        float v = initFromState ? g_hfin[(b0 + row) * UU + col] : 0.0f;
        __nv_bfloat16 hh, ll; split_bf16(v, hh, ll);
        hs_h[row * HSS + col] = hh;
        hs_l[row * HSS + col] = ll;
    }
    __syncthreads();
    CLUSTER_SYNC();    // all inits + buf0 fills done before any remote traffic

    int ph0 = 0, ph1 = 0;

    for (int t = 0; t < Tlen; t++) {
        const int cb = t & 1;

        // ---- prefetch per-step additive term ----
        float xi, xf2, xg, xo;
        if (xw) {
            const float* xr = xw + ((size_t)(b0 + b_l) * Tlen + t) * G4;
            xi  = __ldcg(xr +        u0 + u_l);
            xf2 = __ldcg(xr + 256 +  u0 + u_l);
            xg  = __ldcg(xr + 512 +  u0 + u_l);
            xo  = __ldcg(xr + 768 +  u0 + u_l);
        } else {
            xi = bi; xf2 = bf; xg = bg; xo = bo;
        }

        // ---- wait for this step's h (DSMEM pushes from all 8 CTAs) ----
        if (t > 0) {
            if (cb == 0) { mbar_wait(smb,     (uint32_t)ph0); ph0 ^= 1; }
            else         { mbar_wait(smb + 8, (uint32_t)ph1); ph1 ^= 1; }
        }

        // ---- z = h @ U on tensor cores (3-pass split) ----
        float acc[4] = {0.f, 0.f, 0.f, 0.f};
        const uint32_t bufo = (uint32_t)(cb * HBUF) * 2;
#pragma unroll
        for (int kc = 0; kc < 16; kc++) {
            uint32_t ah[4], al4[4];
            uint32_t off = bufo + aoff + (uint32_t)(kc * 16) * 2;
            ldm_x4(ah,  sh_h + off);
            ldm_x4(al4, sh_l + off);
            mma16816(acc, ah,  bh[kc]);
            mma16816(acc, ah,  bl[kc]);
            mma16816(acc, al4, bh[kc]);
        }
        {
            int r = lane >> 2, cl = wid * 8 + ((lane & 3) << 1);
            *(float2*)&z_s[r * 130 + cl]       = make_float2(acc[0], acc[1]);
            *(float2*)&z_s[(r + 8) * 130 + cl] = make_float2(acc[2], acc[3]);
        }
        __syncthreads();

        // ---- gates: one (b,u) per thread ----
        float zi = z_s[b_l * 130 +      u_l] + xi;
        float zf = z_s[b_l * 130 + 32 + u_l] + xf2;
        float zg = z_s[b_l * 130 + 64 + u_l] + xg;
        float zo = z_s[b_l * 130 + 96 + u_l] + xo;
        float cn = sigm_f(zf) * c_reg + sigm_f(zi) * tanh_f(zg);
        float hn = sigm_f(zo) * tanh_f(cn);
        c_reg = cn;
        __nv_bfloat16 hh, ll; split_bf16(hn, hh, ll);
        {
            size_t oidx = ((size_t)(b0 + b_l) * Tlen + t) * UU + u0 + u_l;
            if (outMode == 1) {
                yhi[oidx] = hh; ylo[oidx] = ll;
            } else if (outMode == 2) {
                yfp[oidx] = hn;
            }
            if (t == Tlen - 1) { g_hfin[gidx] = hn; g_cfin[gidx] = cn; }
        }

        // ---- push h_{t+1} slice into all 8 CTAs' next buffer ----
        if (t + 1 < Tlen) {
            const int nb = (t + 1) & 1;
            const uint32_t off_e = (uint32_t)(nb * HBUF + b_l * HSS + u0 + u_l) * 2;
            const unsigned short hb = *reinterpret_cast<unsigned short*>(&hh);
            const unsigned short lb = *reinterpret_cast<unsigned short*>(&ll);
#pragma unroll
            for (int r = 0; r < 8; r++) {
                st_cluster_u16(mapa_u32(sh_h + off_e, (uint32_t)r), hb);
                st_cluster_u16(mapa_u32(sh_l + off_e, (uint32_t)r), lb);
            }
            __syncthreads();   // all threads' remote stores precede the arrives
            if (tid < 8) {
                mbar_arrive_remote(smb + (nb << 3), (uint32_t)tid);
            }
        }
    }
    CLUSTER_SYNC();    // no CTA exits while peers may still target its smem
}

// ======================= decoder weight combine & dense =======================
__global__ void combine_w_kernel(const float* __restrict__ a, const float* __restrict__ b) {
    int i = blockIdx.x * 256 + threadIdx.x;
    g_wc[i] = a[i] + b[i];
}

__global__ void dense_kernel(const float* __restrict__ h, const float* __restrict__ w,
                             const float* __restrict__ b, float* __restrict__ out) {
    __shared__ float ws[UU * OD];
    for (int i = threadIdx.x; i < UU * OD; i += 256) ws[i] = w[i];
    __syncthreads();
    int idx = blockIdx.x * 256 + threadIdx.x;
    int o   = idx & 7;
    size_t row = idx >> 3;
    float acc = b[o];
    const float* hp = h + row * UU;
#pragma unroll 8
    for (int k = 0; k < UU; k++) acc += hp[k] * ws[k * OD + o];
    out[idx] = acc;
}

// ======================= launch =======================
extern "C" void kernel_launch(void* const* d_in, const int* in_sizes, int n_in,
                              void* d_out, int out_size)
{
    const float* x     = (const float*)d_in[0];
    const float* cnn_w = (const float*)d_in[1];
    const float* cnn_b = (const float*)d_in[2];
    const float* ew0 = (const float*)d_in[3];
    const float* eu0 = (const float*)d_in[4];
    const float* eb0 = (const float*)d_in[5];
    const float* ew1 = (const float*)d_in[6];
    const float* eu1 = (const float*)d_in[7];
    const float* eb1 = (const float*)d_in[8];
    const float* ew2 = (const float*)d_in[9];
    const float* eu2 = (const float*)d_in[10];
    const float* eb2 = (const float*)d_in[11];
    const float* cw  = (const float*)d_in[12];
    const float* cu  = (const float*)d_in[13];
    const float* cb  = (const float*)d_in[14];
    const float* dw  = (const float*)d_in[15];
    const float* db  = (const float*)d_in[16];
    float* out = (float*)d_out;

    __nv_bfloat16 *xch, *xcl, *ah, *al, *wth, *wtl, *uth, *utl, *cwth, *cwtl;
    float *xwp, *hdec, *wc;
    cudaGetSymbolAddress((void**)&xch,  g_xc_hi);
    cudaGetSymbolAddress((void**)&xcl,  g_xc_lo);
    cudaGetSymbolAddress((void**)&ah,   g_a_hi);
    cudaGetSymbolAddress((void**)&al,   g_a_lo);
    cudaGetSymbolAddress((void**)&wth,  g_wt_hi);
    cudaGetSymbolAddress((void**)&wtl,  g_wt_lo);
    cudaGetSymbolAddress((void**)&uth,  g_ut_hi);
    cudaGetSymbolAddress((void**)&utl,  g_ut_lo);
    cudaGetSymbolAddress((void**)&cwth, g_cwt_hi);
    cudaGetSymbolAddress((void**)&cwtl, g_cwt_lo);
    cudaGetSymbolAddress((void**)&xwp,  g_xw);
    cudaGetSymbolAddress((void**)&hdec, g_hdec);
    cudaGetSymbolAddress((void**)&wc,   g_wc);

    const int GEMM_SMEM = 4 * TILE_ELE * 2;
    cudaFuncSetAttribute(mma_gemm<1,1>, cudaFuncAttributeMaxDynamicSharedMemorySize, GEMM_SMEM);
    cudaFuncSetAttribute(mma_gemm<0,0>, cudaFuncAttributeMaxDynamicSharedMemorySize, GEMM_SMEM);

    dim3 scan_grid(16, 8);

    // conv: im2col(split) + HMMA GEMM (bias+ReLU, split-bf16 out)
    im2col_split<<<(int)(((size_t)MTOT * KC) / 256), 256>>>(x);
    wsplit<<<(UU * KC + 255) / 256, 256>>>(cnn_w, cwth, cwtl, KC, UU);
    mma_gemm<1,1><<<dim3(UU / 128, MTOT / 128), 256, GEMM_SMEM>>>(
        xch, xcl, cwth, cwtl, cnn_b, nullptr, ah, al, MTOT, UU, KC);

    // encoder layer 0
    wsplit<<<(UU * G4) / 256, 256>>>(ew0, wth, wtl, UU, G4);
    mma_gemm<0,0><<<dim3(G4 / 128, MTOT / 128), 256, GEMM_SMEM>>>(
        ah, al, wth, wtl, eb0, xwp, nullptr, nullptr, MTOT, G4, UU);
    wsplit<<<(UU * G4) / 256, 256>>>(eu0, uth, utl, UU, G4);
    lstm_scan_mma<<<scan_grid, 512>>>(xwp, nullptr, uth, utl, ah, al, nullptr, TT, 0, 1);

    // encoder layer 1
    wsplit<<<(UU * G4) / 256, 256>>>(ew1, wth, wtl, UU, G4);
    mma_gemm<0,0><<<dim3(G4 / 128, MTOT / 128), 256, GEMM_SMEM>>>(
        ah, al, wth, wtl, eb1, xwp, nullptr, nullptr, MTOT, G4, UU);
    wsplit<<<(UU * G4) / 256, 256>>>(eu1, uth, utl, UU, G4);
    lstm_scan_mma<<<scan_grid, 512>>>(xwp, nullptr, uth, utl, ah, al, nullptr, TT, 0, 1);

    // encoder layer 2 (only final h,c needed)
    wsplit<<<(UU * G4) / 256, 256>>>(ew2, wth, wtl, UU, G4);
    mma_gemm<0,0><<<dim3(G4 / 128, MTOT / 128), 256, GEMM_SMEM>>>(
        ah, al, wth, wtl, eb2, xwp, nullptr, nullptr, MTOT, G4, UU);
    wsplit<<<(UU * G4) / 256, 256>>>(eu2, uth, utl, UU, G4);
    lstm_scan_mma<<<scan_grid, 512>>>(xwp, nullptr, uth, utl, nullptr, nullptr, nullptr, TT, 0, 0);

    // decoder: z = h @ (cell_w + cell_u) + b, 64 steps from (h,c)
    combine_w_kernel<<<(UU * G4) / 256, 256>>>(cw, cu);
    wsplit<<<(UU * G4) / 256, 256>>>(wc, uth, utl, UU, G4);
    lstm_scan_mma<<<scan_grid, 512>>>(nullptr, cb, uth, utl, nullptr, nullptr, hdec, OUTS, 1, 2);

    // dense head
    dense_kernel<<<(BB * OUTS * OD) / 256, 256>>>(hdec, dw, db, out);
}

// round 16
// speedup vs baseline: 1.3703x; 1.3703x over previous
#include <cuda_runtime.h>
#include <cuda_bf16.h>
#include <cstdint>

#define BB    256
#define TT    512
#define FF    64
#define UU    256
#define G4    1024
#define KC    320
#define OUTS  64
#define OD    8
#define MTOT  (BB*TT)   // 131072

// ======================= device scratch =======================
__device__ __nv_bfloat16 g_a_hi [(size_t)MTOT * UU];
__device__ __nv_bfloat16 g_a_lo [(size_t)MTOT * UU];
__device__ __nv_bfloat16 g_wt_hi[G4 * UU];
__device__ __nv_bfloat16 g_wt_lo[G4 * UU];
__device__ __nv_bfloat16 g_ut_hi[G4 * UU];
__device__ __nv_bfloat16 g_ut_lo[G4 * UU];
__device__ __nv_bfloat16 g_cwt_hi[UU * KC];
__device__ __nv_bfloat16 g_cwt_lo[UU * KC];
__device__ float g_xw  [(size_t)MTOT * G4];
__device__ __nv_bfloat16 g_hb_hi[2][BB * UU];   // split h ping-pong
__device__ __nv_bfloat16 g_hb_lo[2][BB * UU];
__device__ float g_hfin[BB * UU];
__device__ float g_cfin[BB * UU];
__device__ float g_hdec[(size_t)BB * OUTS * UU];
__device__ float g_wc  [UU * G4];
__device__ unsigned g_bar[16 * 32];   // per-b-group monotone barrier counters

// ======================= PTX helpers (base-target only) =======================
__device__ __forceinline__ uint32_t smem_u32(const void* p) {
    uint32_t a;
    asm("{ .reg .u64 t; cvta.to.shared.u64 t, %1; cvt.u32.u64 %0, t; }" : "=r"(a) : "l"(p));
    return a;
}
__device__ __forceinline__ void ldm_x4(uint32_t* r, uint32_t addr) {
    asm volatile("ldmatrix.sync.aligned.m8n8.x4.shared.b16 {%0,%1,%2,%3}, [%4];"
        : "=r"(r[0]), "=r"(r[1]), "=r"(r[2]), "=r"(r[3]) : "r"(addr));
}
__device__ __forceinline__ void mma16816(float* d, const uint32_t* a, const uint32_t* b) {
    asm volatile("mma.sync.aligned.m16n8k16.row.col.f32.bf16.bf16.f32 "
        "{%0,%1,%2,%3}, {%4,%5,%6,%7}, {%8,%9}, {%0,%1,%2,%3};"
        : "+f"(d[0]), "+f"(d[1]), "+f"(d[2]), "+f"(d[3])
        : "r"(a[0]), "r"(a[1]), "r"(a[2]), "r"(a[3]), "r"(b[0]), "r"(b[1]));
}

// ======================= misc helpers =======================
__device__ __forceinline__ float sigm_f(float x) {
    return __fdividef(1.0f, 1.0f + __expf(-x));
}
__device__ __forceinline__ float tanh_f(float x) {
    float xc = fminf(fmaxf(x, -15.0f), 15.0f);
    float e  = __expf(-2.0f * xc);
    return __fdividef(1.0f - e, 1.0f + e);
}
__device__ __forceinline__ void split_bf16(float v, __nv_bfloat16& h, __nv_bfloat16& l) {
    h = __float2bfloat16(v);
    l = __float2bfloat16(v - __bfloat162float(h));
}

// Monotone per-group barrier (reset by bar_reset launch before each scan).
// __nanosleep throttles polling (R9/R10). Beats barrier.cluster: cluster.sync
// flushes L1D per step (R12). Beats DSMEM push: scalar remote stores are
// producer-pays serial (R14).
__device__ __forceinline__ void group_sync(int grp, unsigned target) {
    __syncthreads();
    if (threadIdx.x == 0) {
        __threadfence();
        atomicAdd(&g_bar[grp * 32], 1u);
        volatile unsigned* p = &g_bar[grp * 32];
        while (*p < target) { __nanosleep(32); }
        __threadfence();
    }
    __syncthreads();
}

__global__ void bar_reset() {
    if (threadIdx.x < 16) g_bar[threadIdx.x * 32] = 0u;
}

// W[K,N] -> Wt_hi/lo[N,K] bf16 (transpose + split)
__global__ void wsplit(const float* __restrict__ W, __nv_bfloat16* __restrict__ hi,
                       __nv_bfloat16* __restrict__ lo, int K, int N) {
    int idx = blockIdx.x * 256 + threadIdx.x;
    if (idx >= K * N) return;
    int n = idx / K, k = idx % K;
    float v = W[(size_t)k * N + n];
    __nv_bfloat16 h, l; split_bf16(v, h, l);
    hi[idx] = h; lo[idx] = l;
}

// ======================= HMMA split-bf16 GEMM =======================
// CONVA=1: A is gathered from x [B,T,F] via on-the-fly im2col (+split).
#define LDP 72
#define TILE_ELE (128 * LDP)

template<int RELU, int OUTMODE, int CONVA>
__global__ __launch_bounds__(256)
void mma_gemm(const __nv_bfloat16* __restrict__ Ahi, const __nv_bfloat16* __restrict__ Alo,
              const float* __restrict__ xin,
              const __nv_bfloat16* __restrict__ Bhi, const __nv_bfloat16* __restrict__ Blo,
              const float* __restrict__ bias,
              float* __restrict__ C,
              __nv_bfloat16* __restrict__ Chi, __nv_bfloat16* __restrict__ Clo,
              int M, int N, int K)
{
    extern __shared__ __nv_bfloat16 smem[];
    __nv_bfloat16* As_h = smem;
    __nv_bfloat16* As_l = smem + TILE_ELE;
    __nv_bfloat16* Bs_h = smem + 2 * TILE_ELE;
    __nv_bfloat16* Bs_l = smem + 3 * TILE_ELE;

    const int tid  = threadIdx.x;
    const int lane = tid & 31;
    const int wid  = tid >> 5;
    const int wm   = wid & 3;
    const int wn   = wid >> 2;
    const int n0 = blockIdx.x * 128;
    const int m0 = blockIdx.y * 128;

    float acc[2][8][4];
#pragma unroll
    for (int i = 0; i < 2; i++)
#pragma unroll
        for (int j = 0; j < 8; j++)
#pragma unroll
            for (int q = 0; q < 4; q++) acc[i][j][q] = 0.0f;

    const int ar = lane & 15, ac = (lane >> 4) << 3;
    const int br = (lane & 7) + ((lane >> 4) << 3);
    const int bc = ((lane >> 3) & 1) << 3;
    const uint32_t sA_h = smem_u32(As_h), sA_l = smem_u32(As_l);
    const uint32_t sB_h = smem_u32(Bs_h), sB_l = smem_u32(Bs_l);

    for (int k0 = 0; k0 < K; k0 += 64) {
#pragma unroll
        for (int r = 0; r < 4; r++) {
            int unit = tid + r * 256;
            int row = unit >> 3, c8 = (unit & 7) << 3;
            size_t gb = (size_t)(n0 + row) * K + k0 + c8;
            *(uint4*)&Bs_h[row * LDP + c8] = *(const uint4*)&Bhi[gb];
            *(uint4*)&Bs_l[row * LDP + c8] = *(const uint4*)&Blo[gb];
            if (CONVA) {
                // on-the-fly im2col + split: col = k*64+f -> x[b][t+k-2][f]
                int m = m0 + row;
                int b = m >> 9, t = m & 511;
                int kcol = k0 + c8;
                int kk = kcol >> 6, f = kcol & 63;
                int tt = t + kk - 2;
                float4 v0, v1;
                if (tt >= 0 && tt < TT) {
                    const float* xp = xin + ((size_t)b * TT + tt) * FF + f;
                    v0 = *(const float4*)xp;
                    v1 = *(const float4*)(xp + 4);
                } else {
                    v0 = make_float4(0.f, 0.f, 0.f, 0.f);
                    v1 = v0;
                }
                float vals[8] = {v0.x, v0.y, v0.z, v0.w, v1.x, v1.y, v1.z, v1.w};
#pragma unroll
                for (int j = 0; j < 8; j += 2) {
                    __nv_bfloat16 h0, l0, h1, l1;
                    split_bf16(vals[j],     h0, l0);
                    split_bf16(vals[j + 1], h1, l1);
                    *(__nv_bfloat162*)&As_h[row * LDP + c8 + j] = __nv_bfloat162(h0, h1);
                    *(__nv_bfloat162*)&As_l[row * LDP + c8 + j] = __nv_bfloat162(l0, l1);
                }
            } else {
                size_t ga = (size_t)(m0 + row) * K + k0 + c8;
                *(uint4*)&As_h[row * LDP + c8] = *(const uint4*)&Ahi[ga];
                *(uint4*)&As_l[row * LDP + c8] = *(const uint4*)&Alo[ga];
            }
        }
        __syncthreads();

#pragma unroll
        for (int kk = 0; kk < 4; kk++) {
            const int kof = kk * 16;
            uint32_t ah[2][4], al[2][4];
#pragma unroll
            for (int mf = 0; mf < 2; mf++) {
                uint32_t off = (uint32_t)((wm * 32 + mf * 16 + ar) * LDP + kof + ac) * 2;
                ldm_x4(ah[mf], sA_h + off);
                ldm_x4(al[mf], sA_l + off);
            }
#pragma unroll
            for (int g = 0; g < 4; g++) {
                uint32_t bh[4], bl[4];
                uint32_t off = (uint32_t)((wn * 64 + g * 16 + br) * LDP + kof + bc) * 2;
                ldm_x4(bh, sB_h + off);
                ldm_x4(bl, sB_l + off);
#pragma unroll
                for (int mf = 0; mf < 2; mf++) {
                    mma16816(acc[mf][2 * g],     ah[mf], bh);
                    mma16816(acc[mf][2 * g + 1], ah[mf], bh + 2);
                    mma16816(acc[mf][2 * g],     ah[mf], bl);
                    mma16816(acc[mf][2 * g + 1], ah[mf], bl + 2);
                    mma16816(acc[mf][2 * g],     al[mf], bh);
                    mma16816(acc[mf][2 * g + 1], al[mf], bh + 2);
                }
            }
        }
        __syncthreads();
    }

    const int row_base = m0 + wm * 32 + (lane >> 2);
    const int col_loc  = (lane & 3) * 2;
#pragma unroll
    for (int mf = 0; mf < 2; mf++) {
#pragma unroll
        for (int nf = 0; nf < 8; nf++) {
            int c = n0 + wn * 64 + nf * 8 + col_loc;
            float2 bv = *(const float2*)&bias[c];
            int r0 = row_base + mf * 16;
            int r1 = r0 + 8;
            float v00 = acc[mf][nf][0] + bv.x;
            float v01 = acc[mf][nf][1] + bv.y;
            float v10 = acc[mf][nf][2] + bv.x;
            float v11 = acc[mf][nf][3] + bv.y;
            if (RELU) {
                v00 = fmaxf(v00, 0.f); v01 = fmaxf(v01, 0.f);
                v10 = fmaxf(v10, 0.f); v11 = fmaxf(v11, 0.f);
            }
            if (OUTMODE == 0) {
                *(float2*)&C[(size_t)r0 * N + c] = make_float2(v00, v01);
                *(float2*)&C[(size_t)r1 * N + c] = make_float2(v10, v11);
            } else {
                __nv_bfloat16 h0, l0, h1, l1;
                split_bf16(v00, h0, l0); split_bf16(v01, h1, l1);
                *(__nv_bfloat162*)&Chi[(size_t)r0 * N + c] = __nv_bfloat162(h0, h1);
                *(__nv_bfloat162*)&Clo[(size_t)r0 * N + c] = __nv_bfloat162(l0, l1);
                split_bf16(v10, h0, l0); split_bf16(v11, h1, l1);
                *(__nv_bfloat162*)&Chi[(size_t)r1 * N + c] = __nv_bfloat162(h0, h1);
                *(__nv_bfloat162*)&Clo[(size_t)r1 * N + c] = __nv_bfloat162(l0, l1);
            }
        }
    }
}

// ======================= persistent HMMA LSTM scan =======================
// grid (16,8): blockIdx.x = b-group (16 batch rows), blockIdx.y = u-tile
// (32 units -> 128 gate cols). 512 threads = 16 warps; warp wid covers gate
// wid>>2, units (wid&3)*8 + lane/4. One block per SM. Software monotone
// barrier (8 arrivals). MMA uses 3 INDEPENDENT accumulator chains (hh/hl/lh)
// to break the 48-deep RAW serialization on a single accumulator.
#define HSS 264

__global__ __launch_bounds__(512, 1)
void lstm_scan_mma(const float* __restrict__ xw, const float* __restrict__ bias,
                   const __nv_bfloat16* __restrict__ Uth,
                   const __nv_bfloat16* __restrict__ Utl,
                   __nv_bfloat16* __restrict__ yhi, __nv_bfloat16* __restrict__ ylo,
                   float* __restrict__ yfp,
                   int Tlen, int initFromState, int outMode)
{
    __shared__ __nv_bfloat16 hs_h[16 * HSS];
    __shared__ __nv_bfloat16 hs_l[16 * HSS];
    __shared__ float z_s[16 * 130];

    const int tid = threadIdx.x, lane = tid & 31, wid = tid >> 5;
    const int grp = blockIdx.x;
    const int b0 = blockIdx.x * 16, u0 = blockIdx.y * 32;

    // ---- register-resident B fragments (m16n8k16 row.col B layout) ----
    const int gate = wid >> 2;
    const int jB = gate * UU + u0 + ((wid & 3) << 3) + (lane >> 2);
    const __nv_bfloat16* uhp = Uth + (size_t)jB * UU;
    const __nv_bfloat16* ulp = Utl + (size_t)jB * UU;
    uint32_t bh[16][2], bl[16][2];
    const int kq = (lane & 3) << 1;
#pragma unroll
    for (int kc = 0; kc < 16; kc++) {
        bh[kc][0] = *(const uint32_t*)&uhp[kc * 16 + kq];
        bh[kc][1] = *(const uint32_t*)&uhp[kc * 16 + kq + 8];
        bl[kc][0] = *(const uint32_t*)&ulp[kc * 16 + kq];
        bl[kc][1] = *(const uint32_t*)&ulp[kc * 16 + kq + 8];
    }

    // ---- per-thread state (one (b,u) cell), coalesced mapping ----
    const int b_l = tid >> 5, u_l = tid & 31;
    const int gidx = (b0 + b_l) * UU + (u0 + u_l);
    float c_reg = initFromState ? g_cfin[gidx] : 0.0f;
    {
        float h0v = initFromState ? g_hfin[gidx] : 0.0f;
        __nv_bfloat16 hh, ll; split_bf16(h0v, hh, ll);
        g_hb_hi[0][gidx] = hh; g_hb_lo[0][gidx] = ll;
    }

    // decoder-mode bias (encoder xw already includes bias)
    float bi = 0.f, bf = 0.f, bg = 0.f, bo = 0.f;
    if (!xw) {
        bi = bias[u0 + u_l];        bf = bias[256 + u0 + u_l];
        bg = bias[512 + u0 + u_l];  bo = bias[768 + u0 + u_l];
    }

    const uint32_t sh_h = smem_u32(hs_h);
    const uint32_t sh_l = smem_u32(hs_l);
    const uint32_t aoff = (uint32_t)((lane & 15) * HSS + ((lane >> 4) << 3)) * 2;

    group_sync(grp, 8u);                        // barrier #0

    for (int t = 0; t < Tlen; t++) {
        // ---- prefetch per-step additive term (overlaps staging + MMA) ----
        float xi, xf2, xg, xo;
        if (xw) {
            const float* xr = xw + ((size_t)(b0 + b_l) * Tlen + t) * G4;
            xi  = __ldcg(xr +        u0 + u_l);
            xf2 = __ldcg(xr + 256 +  u0 + u_l);
            xg  = __ldcg(xr + 512 +  u0 + u_l);
            xo  = __ldcg(xr + 768 +  u0 + u_l);
        } else {
            xi = bi; xf2 = bf; xg = bg; xo = bo;
        }

        // ---- stage split h: plain bf16 copy (512 uint4 units per array) ----
        {
            const uint4* sh = (const uint4*)(g_hb_hi[t & 1] + b0 * UU);
            const uint4* sl = (const uint4*)(g_hb_lo[t & 1] + b0 * UU);
            int row = tid >> 5, c = (tid & 31) << 3;
            *(uint4*)&hs_h[row * HSS + c] = __ldcg(sh + tid);
            *(uint4*)&hs_l[row * HSS + c] = __ldcg(sl + tid);
        }
        __syncthreads();

        // ---- z = h @ U: 3 independent accumulator chains ----
        float a0[4] = {0.f, 0.f, 0.f, 0.f};
        float a1[4] = {0.f, 0.f, 0.f, 0.f};
        float a2[4] = {0.f, 0.f, 0.f, 0.f};
#pragma unroll
        for (int kc = 0; kc < 16; kc++) {
            uint32_t ah[4], al4[4];
            uint32_t off = aoff + (uint32_t)(kc * 16) * 2;
            ldm_x4(ah,  sh_h + off);
            ldm_x4(al4, sh_l + off);
            mma16816(a0, ah,  bh[kc]);
            mma16816(a1, ah,  bl[kc]);
            mma16816(a2, al4, bh[kc]);
        }
        {
            int r = lane >> 2, cl = wid * 8 + ((lane & 3) << 1);
            *(float2*)&z_s[r * 130 + cl] =
                make_float2(a0[0] + a1[0] + a2[0], a0[1] + a1[1] + a2[1]);
            *(float2*)&z_s[(r + 8) * 130 + cl] =
                make_float2(a0[2] + a1[2] + a2[2], a0[3] + a1[3] + a2[3]);
        }
        __syncthreads();

        // ---- gates: one (b,u) per thread (coalesced) ----
        {
            float zi = z_s[b_l * 130 +      u_l] + xi;
            float zf = z_s[b_l * 130 + 32 + u_l] + xf2;
            float zg = z_s[b_l * 130 + 64 + u_l] + xg;
            float zo = z_s[b_l * 130 + 96 + u_l] + xo;
            float cn = sigm_f(zf) * c_reg + sigm_f(zi) * tanh_f(zg);
            float hn = sigm_f(zo) * tanh_f(cn);
            c_reg = cn;
            __nv_bfloat16 hh, ll; split_bf16(hn, hh, ll);
            g_hb_hi[(t + 1) & 1][gidx] = hh;
            g_hb_lo[(t + 1) & 1][gidx] = ll;
            size_t oidx = ((size_t)(b0 + b_l) * Tlen + t) * UU + u0 + u_l;
            if (outMode == 1) {
                yhi[oidx] = hh; ylo[oidx] = ll;
            } else if (outMode == 2) {
                yfp[oidx] = hn;
            }
            if (t == Tlen - 1) { g_hfin[gidx] = hn; g_cfin[gidx] = cn; }
        }
        if (t + 1 < Tlen)
            group_sync(grp, 8u * (unsigned)(t + 2));   // barrier #(t+1)
    }
}

// ======================= decoder weight combine & dense =======================
__global__ void combine_w_kernel(const float* __restrict__ a, const float* __restrict__ b) {
    int i = blockIdx.x * 256 + threadIdx.x;
    g_wc[i] = a[i] + b[i];
}

__global__ void dense_kernel(const float* __restrict__ h, const float* __restrict__ w,
                             const float* __restrict__ b, float* __restrict__ out) {
    __shared__ float ws[UU * OD];
    for (int i = threadIdx.x; i < UU * OD; i += 256) ws[i] = w[i];
    __syncthreads();
    int idx = blockIdx.x * 256 + threadIdx.x;
    int o   = idx & 7;
    size_t row = idx >> 3;
    float acc = b[o];
    const float* hp = h + row * UU;
#pragma unroll 8
    for (int k = 0; k < UU; k++) acc += hp[k] * ws[k * OD + o];
    out[idx] = acc;
}

// ======================= launch =======================
extern "C" void kernel_launch(void* const* d_in, const int* in_sizes, int n_in,
                              void* d_out, int out_size)
{
    const float* x     = (const float*)d_in[0];
    const float* cnn_w = (const float*)d_in[1];
    const float* cnn_b = (const float*)d_in[2];
    const float* ew0 = (const float*)d_in[3];
    const float* eu0 = (const float*)d_in[4];
    const float* eb0 = (const float*)d_in[5];
    const float* ew1 = (const float*)d_in[6];
    const float* eu1 = (const float*)d_in[7];
    const float* eb1 = (const float*)d_in[8];
    const float* ew2 = (const float*)d_in[9];
    const float* eu2 = (const float*)d_in[10];
    const float* eb2 = (const float*)d_in[11];
    const float* cw  = (const float*)d_in[12];
    const float* cu  = (const float*)d_in[13];
    const float* cb  = (const float*)d_in[14];
    const float* dw  = (const float*)d_in[15];
    const float* db  = (const float*)d_in[16];
    float* out = (float*)d_out;

    __nv_bfloat16 *ah, *al, *wth, *wtl, *uth, *utl, *cwth, *cwtl;
    float *xwp, *hdec, *wc;
    cudaGetSymbolAddress((void**)&ah,   g_a_hi);
    cudaGetSymbolAddress((void**)&al,   g_a_lo);
    cudaGetSymbolAddress((void**)&wth,  g_wt_hi);
    cudaGetSymbolAddress((void**)&wtl,  g_wt_lo);
    cudaGetSymbolAddress((void**)&uth,  g_ut_hi);
    cudaGetSymbolAddress((void**)&utl,  g_ut_lo);
    cudaGetSymbolAddress((void**)&cwth, g_cwt_hi);
    cudaGetSymbolAddress((void**)&cwtl, g_cwt_lo);
    cudaGetSymbolAddress((void**)&xwp,  g_xw);
    cudaGetSymbolAddress((void**)&hdec, g_hdec);
    cudaGetSymbolAddress((void**)&wc,   g_wc);

    const int GEMM_SMEM = 4 * TILE_ELE * 2;
    cudaFuncSetAttribute(mma_gemm<1,1,1>, cudaFuncAttributeMaxDynamicSharedMemorySize, GEMM_SMEM);
    cudaFuncSetAttribute(mma_gemm<0,0,0>, cudaFuncAttributeMaxDynamicSharedMemorySize, GEMM_SMEM);

    dim3 scan_grid(16, 8);

    // conv: fused im2col+split inside the GEMM A-loader (bias+ReLU, split out)
    wsplit<<<(UU * KC + 255) / 256, 256>>>(cnn_w, cwth, cwtl, KC, UU);
    mma_gemm<1,1,1><<<dim3(UU / 128, MTOT / 128), 256, GEMM_SMEM>>>(
        nullptr, nullptr, x, cwth, cwtl, cnn_b, nullptr, ah, al, MTOT, UU, KC);

    // encoder layer 0
    wsplit<<<(UU * G4) / 256, 256>>>(ew0, wth, wtl, UU, G4);
    mma_gemm<0,0,0><<<dim3(G4 / 128, MTOT / 128), 256, GEMM_SMEM>>>(
        ah, al, nullptr, wth, wtl, eb0, xwp, nullptr, nullptr, MTOT, G4, UU);
    wsplit<<<(UU * G4) / 256, 256>>>(eu0, uth, utl, UU, G4);
    bar_reset<<<1, 32>>>();
    lstm_scan_mma<<<scan_grid, 512>>>(xwp, nullptr, uth, utl, ah, al, nullptr, TT, 0, 1);

    // encoder layer 1
    wsplit<<<(UU * G4) / 256, 256>>>(ew1, wth, wtl, UU, G4);
    mma_gemm<0,0,0><<<dim3(G4 / 128, MTOT / 128), 256, GEMM_SMEM>>>(
        ah, al, nullptr, wth, wtl, eb1, xwp, nullptr, nullptr, MTOT, G4, UU);
    wsplit<<<(UU * G4) / 256, 256>>>(eu1, uth, utl, UU, G4);
    bar_reset<<<1, 32>>>();
    lstm_scan_mma<<<scan_grid, 512>>>(xwp, nullptr, uth, utl, ah, al, nullptr, TT, 0, 1);

    // encoder layer 2 (only final h,c needed)
    wsplit<<<(UU * G4) / 256, 256>>>(ew2, wth, wtl, UU, G4);
    mma_gemm<0,0,0><<<dim3(G4 / 128, MTOT / 128), 256, GEMM_SMEM>>>(
        ah, al, nullptr, wth, wtl, eb2, xwp, nullptr, nullptr, MTOT, G4, UU);
    wsplit<<<(UU * G4) / 256, 256>>>(eu2, uth, utl, UU, G4);
    bar_reset<<<1, 32>>>();
    lstm_scan_mma<<<scan_grid, 512>>>(xwp, nullptr, uth, utl, nullptr, nullptr, nullptr, TT, 0, 0);

    // decoder: z = h @ (cell_w + cell_u) + b, 64 steps from (h,c)
    combine_w_kernel<<<(UU * G4) / 256, 256>>>(cw, cu);
    wsplit<<<(UU * G4) / 256, 256>>>(wc, uth, utl, UU, G4);
    bar_reset<<<1, 32>>>();
    lstm_scan_mma<<<scan_grid, 512>>>(nullptr, cb, uth, utl, nullptr, nullptr, hdec, OUTS, 1, 2);

    // dense head
    dense_kernel<<<(BB * OUTS * OD) / 256, 256>>>(hdec, dw, db, out);
}

// round 17
// speedup vs baseline: 1.4491x; 1.0575x over previous
#include <cuda_runtime.h>
#include <cuda_bf16.h>
#include <cstdint>

#define BB    256
#define TT    512
#define FF    64
#define UU    256
#define G4    1024
#define KC    320
#define OUTS  64
#define OD    8
#define MTOT  (BB*TT)   // 131072

// ======================= device scratch =======================
__device__ __nv_bfloat16 g_a_hi [(size_t)MTOT * UU];
__device__ __nv_bfloat16 g_a_lo [(size_t)MTOT * UU];
__device__ __nv_bfloat16 g_wt_hi[G4 * UU];
__device__ __nv_bfloat16 g_wt_lo[G4 * UU];
__device__ __nv_bfloat16 g_ut_hi[G4 * UU];
__device__ __nv_bfloat16 g_ut_lo[G4 * UU];
__device__ __nv_bfloat16 g_cwt_hi[UU * KC];
__device__ __nv_bfloat16 g_cwt_lo[UU * KC];
__device__ float g_xw  [(size_t)MTOT * G4];
__device__ __nv_bfloat16 g_hb_hi[2][BB * UU];   // split h ping-pong
__device__ __nv_bfloat16 g_hb_lo[2][BB * UU];
__device__ float g_hfin[BB * UU];
__device__ float g_cfin[BB * UU];
__device__ float g_hdec[(size_t)BB * OUTS * UU];
__device__ float g_wc  [UU * G4];
__device__ unsigned g_bar[16 * 32];   // per-b-group monotone barrier counters

// ======================= PTX helpers (base-target only) =======================
__device__ __forceinline__ uint32_t smem_u32(const void* p) {
    uint32_t a;
    asm("{ .reg .u64 t; cvta.to.shared.u64 t, %1; cvt.u32.u64 %0, t; }" : "=r"(a) : "l"(p));
    return a;
}
__device__ __forceinline__ void ldm_x4(uint32_t* r, uint32_t addr) {
    asm volatile("ldmatrix.sync.aligned.m8n8.x4.shared.b16 {%0,%1,%2,%3}, [%4];"
        : "=r"(r[0]), "=r"(r[1]), "=r"(r[2]), "=r"(r[3]) : "r"(addr));
}
__device__ __forceinline__ void mma16816(float* d, const uint32_t* a, const uint32_t* b) {
    asm volatile("mma.sync.aligned.m16n8k16.row.col.f32.bf16.bf16.f32 "
        "{%0,%1,%2,%3}, {%4,%5,%6,%7}, {%8,%9}, {%0,%1,%2,%3};"
        : "+f"(d[0]), "+f"(d[1]), "+f"(d[2]), "+f"(d[3])
        : "r"(a[0]), "r"(a[1]), "r"(a[2]), "r"(a[3]), "r"(b[0]), "r"(b[1]));
}
__device__ __forceinline__ void cpasync16(uint32_t dst, const void* src) {
    asm volatile("cp.async.cg.shared.global [%0], [%1], 16;"
                 :: "r"(dst), "l"(src) : "memory");
}
#define CP_COMMIT() asm volatile("cp.async.commit_group;" ::: "memory")
#define CP_WAIT0()  asm volatile("cp.async.wait_group 0;" ::: "memory")

// ======================= misc helpers =======================
__device__ __forceinline__ float sigm_f(float x) {
    return __fdividef(1.0f, 1.0f + __expf(-x));
}
__device__ __forceinline__ float tanh_f(float x) {
    float xc = fminf(fmaxf(x, -15.0f), 15.0f);
    float e  = __expf(-2.0f * xc);
    return __fdividef(1.0f - e, 1.0f + e);
}
__device__ __forceinline__ void split_bf16(float v, __nv_bfloat16& h, __nv_bfloat16& l) {
    h = __float2bfloat16(v);
    l = __float2bfloat16(v - __bfloat162float(h));
}

// Monotone per-group barrier (reset by bar_reset launch before each scan).
__device__ __forceinline__ void group_sync(int grp, unsigned target) {
    __syncthreads();
    if (threadIdx.x == 0) {
        __threadfence();
        atomicAdd(&g_bar[grp * 32], 1u);
        volatile unsigned* p = &g_bar[grp * 32];
        while (*p < target) { __nanosleep(32); }
        __threadfence();
    }
    __syncthreads();
}

__global__ void bar_reset() {
    if (threadIdx.x < 16) g_bar[threadIdx.x * 32] = 0u;
}

// W[K,N] -> Wt_hi/lo[N,K] bf16 (transpose + split)
__global__ void wsplit(const float* __restrict__ W, __nv_bfloat16* __restrict__ hi,
                       __nv_bfloat16* __restrict__ lo, int K, int N) {
    int idx = blockIdx.x * 256 + threadIdx.x;
    if (idx >= K * N) return;
    int n = idx / K, k = idx % K;
    float v = W[(size_t)k * N + n];
    __nv_bfloat16 h, l; split_bf16(v, h, l);
    hi[idx] = h; lo[idx] = l;
}

// ======================= HMMA split-bf16 GEMM (cp.async pipelined) ==========
#define LDP 72
#define TILE_ELE (128 * LDP)          // elements per tile (18432 B)
#define STAGE_ELE (4 * TILE_ELE)      // Ah, Al, Bh, Bl
#define GEMM_SMEM (2 * STAGE_ELE * 2) // 147456 B

template<int CONVA>
__device__ __forceinline__ void gemm_load_stage(
    __nv_bfloat16* base, int tid, int m0, int n0, int k0, int K,
    const __nv_bfloat16* Ahi, const __nv_bfloat16* Alo, const float* xin,
    const __nv_bfloat16* Bhi, const __nv_bfloat16* Blo)
{
    const uint32_t sb = smem_u32(base);
#pragma unroll
    for (int r = 0; r < 4; r++) {
        int unit = tid + r * 256;
        int row = unit >> 3, c8 = (unit & 7) << 3;
        size_t gb = (size_t)(n0 + row) * K + k0 + c8;
        cpasync16(sb + (uint32_t)(2 * TILE_ELE + row * LDP + c8) * 2, &Bhi[gb]);
        cpasync16(sb + (uint32_t)(3 * TILE_ELE + row * LDP + c8) * 2, &Blo[gb]);
        if (CONVA) {
            // fused im2col + split: col = k*64+f -> x[b][t+k-2][f]
            int m = m0 + row;
            int b = m >> 9, t = m & 511;
            int kcol = k0 + c8;
            int kk = kcol >> 6, f = kcol & 63;
            int tt = t + kk - 2;
            float4 v0, v1;
            if (tt >= 0 && tt < TT) {
                const float* xp = xin + ((size_t)b * TT + tt) * FF + f;
                v0 = *(const float4*)xp;
                v1 = *(const float4*)(xp + 4);
            } else {
                v0 = make_float4(0.f, 0.f, 0.f, 0.f);
                v1 = v0;
            }
            float vals[8] = {v0.x, v0.y, v0.z, v0.w, v1.x, v1.y, v1.z, v1.w};
#pragma unroll
            for (int j = 0; j < 8; j += 2) {
                __nv_bfloat16 h0, l0, h1, l1;
                split_bf16(vals[j],     h0, l0);
                split_bf16(vals[j + 1], h1, l1);
                *(__nv_bfloat162*)&base[row * LDP + c8 + j] = __nv_bfloat162(h0, h1);
                *(__nv_bfloat162*)&base[TILE_ELE + row * LDP + c8 + j] = __nv_bfloat162(l0, l1);
            }
        } else {
            size_t ga = (size_t)(m0 + row) * K + k0 + c8;
            cpasync16(sb + (uint32_t)(row * LDP + c8) * 2, &Ahi[ga]);
            cpasync16(sb + (uint32_t)(TILE_ELE + row * LDP + c8) * 2, &Alo[ga]);
        }
    }
    CP_COMMIT();
}

template<int RELU, int OUTMODE, int CONVA>
__global__ __launch_bounds__(256)
void mma_gemm(const __nv_bfloat16* __restrict__ Ahi, const __nv_bfloat16* __restrict__ Alo,
              const float* __restrict__ xin,
              const __nv_bfloat16* __restrict__ Bhi, const __nv_bfloat16* __restrict__ Blo,
              const float* __restrict__ bias,
              float* __restrict__ C,
              __nv_bfloat16* __restrict__ Chi, __nv_bfloat16* __restrict__ Clo,
              int M, int N, int K)
{
    extern __shared__ __nv_bfloat16 smem[];

    const int tid  = threadIdx.x;
    const int lane = tid & 31;
    const int wid  = tid >> 5;
    const int wm   = wid & 3;
    const int wn   = wid >> 2;
    const int n0 = blockIdx.x * 128;
    const int m0 = blockIdx.y * 128;

    float acc[2][8][4];
#pragma unroll
    for (int i = 0; i < 2; i++)
#pragma unroll
        for (int j = 0; j < 8; j++)
#pragma unroll
            for (int q = 0; q < 4; q++) acc[i][j][q] = 0.0f;

    const int ar = lane & 15, ac = (lane >> 4) << 3;
    const int br = (lane & 7) + ((lane >> 4) << 3);
    const int bc = ((lane >> 3) & 1) << 3;

    const int nst = K >> 6;
    gemm_load_stage<CONVA>(smem, tid, m0, n0, 0, K, Ahi, Alo, xin, Bhi, Blo);
    int cur = 0;

    for (int s = 0; s < nst; s++) {
        CP_WAIT0();
        __syncthreads();
        if (s + 1 < nst)
            gemm_load_stage<CONVA>(smem + (1 - cur) * STAGE_ELE, tid, m0, n0,
                                   (s + 1) << 6, K, Ahi, Alo, xin, Bhi, Blo);

        const uint32_t sA_h = smem_u32(smem + cur * STAGE_ELE);
        const uint32_t sA_l = sA_h + TILE_ELE * 2;
        const uint32_t sB_h = sA_h + 2 * TILE_ELE * 2;
        const uint32_t sB_l = sA_h + 3 * TILE_ELE * 2;

#pragma unroll
        for (int kk = 0; kk < 4; kk++) {
            const int kof = kk * 16;
            uint32_t ah[2][4], al[2][4];
#pragma unroll
            for (int mf = 0; mf < 2; mf++) {
                uint32_t off = (uint32_t)((wm * 32 + mf * 16 + ar) * LDP + kof + ac) * 2;
                ldm_x4(ah[mf], sA_h + off);
                ldm_x4(al[mf], sA_l + off);
            }
#pragma unroll
            for (int g = 0; g < 4; g++) {
                uint32_t bh[4], bl[4];
                uint32_t off = (uint32_t)((wn * 64 + g * 16 + br) * LDP + kof + bc) * 2;
                ldm_x4(bh, sB_h + off);
                ldm_x4(bl, sB_l + off);
#pragma unroll
                for (int mf = 0; mf < 2; mf++) {
                    mma16816(acc[mf][2 * g],     ah[mf], bh);
                    mma16816(acc[mf][2 * g + 1], ah[mf], bh + 2);
                    mma16816(acc[mf][2 * g],     ah[mf], bl);
                    mma16816(acc[mf][2 * g + 1], ah[mf], bl + 2);
                    mma16816(acc[mf][2 * g],     al[mf], bh);
                    mma16816(acc[mf][2 * g + 1], al[mf], bh + 2);
                }
            }
        }
        cur ^= 1;
        __syncthreads();
    }

    const int row_base = m0 + wm * 32 + (lane >> 2);
    const int col_loc  = (lane & 3) * 2;
#pragma unroll
    for (int mf = 0; mf < 2; mf++) {
#pragma unroll
        for (int nf = 0; nf < 8; nf++) {
            int c = n0 + wn * 64 + nf * 8 + col_loc;
            float2 bv = *(const float2*)&bias[c];
            int r0 = row_base + mf * 16;
            int r1 = r0 + 8;
            float v00 = acc[mf][nf][0] + bv.x;
            float v01 = acc[mf][nf][1] + bv.y;
            float v10 = acc[mf][nf][2] + bv.x;
            float v11 = acc[mf][nf][3] + bv.y;
            if (RELU) {
                v00 = fmaxf(v00, 0.f); v01 = fmaxf(v01, 0.f);
                v10 = fmaxf(v10, 0.f); v11 = fmaxf(v11, 0.f);
            }
            if (OUTMODE == 0) {
                *(float2*)&C[(size_t)r0 * N + c] = make_float2(v00, v01);
                *(float2*)&C[(size_t)r1 * N + c] = make_float2(v10, v11);
            } else {
                __nv_bfloat16 h0, l0, h1, l1;
                split_bf16(v00, h0, l0); split_bf16(v01, h1, l1);
                *(__nv_bfloat162*)&Chi[(size_t)r0 * N + c] = __nv_bfloat162(h0, h1);
                *(__nv_bfloat162*)&Clo[(size_t)r0 * N + c] = __nv_bfloat162(l0, l1);
                split_bf16(v10, h0, l0); split_bf16(v11, h1, l1);
                *(__nv_bfloat162*)&Chi[(size_t)r1 * N + c] = __nv_bfloat162(h0, h1);
                *(__nv_bfloat162*)&Clo[(size_t)r1 * N + c] = __nv_bfloat162(l0, l1);
            }
        }
    }
}

// ======================= persistent HMMA LSTM scan =======================
// grid (16,8): blockIdx.x = b-group (16 batch rows), blockIdx.y = u-tile
// (32 units -> 128 gate cols). 512 threads = 16 warps. One block per SM.
// Software monotone barrier (8 arrivals). 3 independent accumulator chains.
#define HSS 264

__global__ __launch_bounds__(512, 1)
void lstm_scan_mma(const float* __restrict__ xw, const float* __restrict__ bias,
                   const __nv_bfloat16* __restrict__ Uth,
                   const __nv_bfloat16* __restrict__ Utl,
                   __nv_bfloat16* __restrict__ yhi, __nv_bfloat16* __restrict__ ylo,
                   float* __restrict__ yfp,
                   int Tlen, int initFromState, int outMode)
{
    __shared__ __nv_bfloat16 hs_h[16 * HSS];
    __shared__ __nv_bfloat16 hs_l[16 * HSS];
    __shared__ float z_s[16 * 130];

    const int tid = threadIdx.x, lane = tid & 31, wid = tid >> 5;
    const int grp = blockIdx.x;
    const int b0 = blockIdx.x * 16, u0 = blockIdx.y * 32;

    const int gate = wid >> 2;
    const int jB = gate * UU + u0 + ((wid & 3) << 3) + (lane >> 2);
    const __nv_bfloat16* uhp = Uth + (size_t)jB * UU;
    const __nv_bfloat16* ulp = Utl + (size_t)jB * UU;
    uint32_t bh[16][2], bl[16][2];
    const int kq = (lane & 3) << 1;
#pragma unroll
    for (int kc = 0; kc < 16; kc++) {
        bh[kc][0] = *(const uint32_t*)&uhp[kc * 16 + kq];
        bh[kc][1] = *(const uint32_t*)&uhp[kc * 16 + kq + 8];
        bl[kc][0] = *(const uint32_t*)&ulp[kc * 16 + kq];
        bl[kc][1] = *(const uint32_t*)&ulp[kc * 16 + kq + 8];
    }

    const int b_l = tid >> 5, u_l = tid & 31;
    const int gidx = (b0 + b_l) * UU + (u0 + u_l);
    float c_reg = initFromState ? g_cfin[gidx] : 0.0f;
    {
        float h0v = initFromState ? g_hfin[gidx] : 0.0f;
        __nv_bfloat16 hh, ll; split_bf16(h0v, hh, ll);
        g_hb_hi[0][gidx] = hh; g_hb_lo[0][gidx] = ll;
    }

    float bi = 0.f, bf = 0.f, bg = 0.f, bo = 0.f;
    if (!xw) {
        bi = bias[u0 + u_l];        bf = bias[256 + u0 + u_l];
        bg = bias[512 + u0 + u_l];  bo = bias[768 + u0 + u_l];
    }

    const uint32_t sh_h = smem_u32(hs_h);
    const uint32_t sh_l = smem_u32(hs_l);
    const uint32_t aoff = (uint32_t)((lane & 15) * HSS + ((lane >> 4) << 3)) * 2;

    group_sync(grp, 8u);

    for (int t = 0; t < Tlen; t++) {
        float xi, xf2, xg, xo;
        if (xw) {
            const float* xr = xw + ((size_t)(b0 + b_l) * Tlen + t) * G4;
            xi  = __ldcg(xr +        u0 + u_l);
            xf2 = __ldcg(xr + 256 +  u0 + u_l);
            xg  = __ldcg(xr + 512 +  u0 + u_l);
            xo  = __ldcg(xr + 768 +  u0 + u_l);
        } else {
            xi = bi; xf2 = bf; xg = bg; xo = bo;
        }

        {
            const uint4* sh = (const uint4*)(g_hb_hi[t & 1] + b0 * UU);
            const uint4* sl = (const uint4*)(g_hb_lo[t & 1] + b0 * UU);
            int row = tid >> 5, c = (tid & 31) << 3;
            *(uint4*)&hs_h[row * HSS + c] = __ldcg(sh + tid);
            *(uint4*)&hs_l[row * HSS + c] = __ldcg(sl + tid);
        }
        __syncthreads();

        float a0[4] = {0.f, 0.f, 0.f, 0.f};
        float a1[4] = {0.f, 0.f, 0.f, 0.f};
        float a2[4] = {0.f, 0.f, 0.f, 0.f};
#pragma unroll
        for (int kc = 0; kc < 16; kc++) {
            uint32_t ah[4], al4[4];
            uint32_t off = aoff + (uint32_t)(kc * 16) * 2;
            ldm_x4(ah,  sh_h + off);
            ldm_x4(al4, sh_l + off);
            mma16816(a0, ah,  bh[kc]);
            mma16816(a1, ah,  bl[kc]);
            mma16816(a2, al4, bh[kc]);
        }
        {
            int r = lane >> 2, cl = wid * 8 + ((lane & 3) << 1);
            *(float2*)&z_s[r * 130 + cl] =
                make_float2(a0[0] + a1[0] + a2[0], a0[1] + a1[1] + a2[1]);
            *(float2*)&z_s[(r + 8) * 130 + cl] =
                make_float2(a0[2] + a1[2] + a2[2], a0[3] + a1[3] + a2[3]);
        }
        __syncthreads();

        {
            float zi = z_s[b_l * 130 +      u_l] + xi;
            float zf = z_s[b_l * 130 + 32 + u_l] + xf2;
            float zg = z_s[b_l * 130 + 64 + u_l] + xg;
            float zo = z_s[b_l * 130 + 96 + u_l] + xo;
            float cn = sigm_f(zf) * c_reg + sigm_f(zi) * tanh_f(zg);
            float hn = sigm_f(zo) * tanh_f(cn);
            c_reg = cn;
            __nv_bfloat16 hh, ll; split_bf16(hn, hh, ll);
            g_hb_hi[(t + 1) & 1][gidx] = hh;
            g_hb_lo[(t + 1) & 1][gidx] = ll;
            size_t oidx = ((size_t)(b0 + b_l) * Tlen + t) * UU + u0 + u_l;
            if (outMode == 1) {
                yhi[oidx] = hh; ylo[oidx] = ll;
            } else if (outMode == 2) {
                yfp[oidx] = hn;
            }
            if (t == Tlen - 1) { g_hfin[gidx] = hn; g_cfin[gidx] = cn; }
        }
        if (t + 1 < Tlen)
            group_sync(grp, 8u * (unsigned)(t + 2));
    }
}

// ======================= decoder weight combine & dense =======================
__global__ void combine_w_kernel(const float* __restrict__ a, const float* __restrict__ b) {
    int i = blockIdx.x * 256 + threadIdx.x;
    g_wc[i] = a[i] + b[i];
}

__global__ void dense_kernel(const float* __restrict__ h, const float* __restrict__ w,
                             const float* __restrict__ b, float* __restrict__ out) {
    __shared__ float ws[UU * OD];
    for (int i = threadIdx.x; i < UU * OD; i += 256) ws[i] = w[i];
    __syncthreads();
    int idx = blockIdx.x * 256 + threadIdx.x;
    int o   = idx & 7;
    size_t row = idx >> 3;
    float acc = b[o];
    const float* hp = h + row * UU;
#pragma unroll 8
    for (int k = 0; k < UU; k++) acc += hp[k] * ws[k * OD + o];
    out[idx] = acc;
}

// ======================= launch =======================
extern "C" void kernel_launch(void* const* d_in, const int* in_sizes, int n_in,
                              void* d_out, int out_size)
{
    const float* x     = (const float*)d_in[0];
    const float* cnn_w = (const float*)d_in[1];
    const float* cnn_b = (const float*)d_in[2];
    const float* ew0 = (const float*)d_in[3];
    const float* eu0 = (const float*)d_in[4];
    const float* eb0 = (const float*)d_in[5];
    const float* ew1 = (const float*)d_in[6];
    const float* eu1 = (const float*)d_in[7];
    const float* eb1 = (const float*)d_in[8];
    const float* ew2 = (const float*)d_in[9];
    const float* eu2 = (const float*)d_in[10];
    const float* eb2 = (const float*)d_in[11];
    const float* cw  = (const float*)d_in[12];
    const float* cu  = (const float*)d_in[13];
    const float* cb  = (const float*)d_in[14];
    const float* dw  = (const float*)d_in[15];
    const float* db  = (const float*)d_in[16];
    float* out = (float*)d_out;

    __nv_bfloat16 *ah, *al, *wth, *wtl, *uth, *utl, *cwth, *cwtl;
    float *xwp, *hdec, *wc;
    cudaGetSymbolAddress((void**)&ah,   g_a_hi);
    cudaGetSymbolAddress((void**)&al,   g_a_lo);
    cudaGetSymbolAddress((void**)&wth,  g_wt_hi);
    cudaGetSymbolAddress((void**)&wtl,  g_wt_lo);
    cudaGetSymbolAddress((void**)&uth,  g_ut_hi);
    cudaGetSymbolAddress((void**)&utl,  g_ut_lo);
    cudaGetSymbolAddress((void**)&cwth, g_cwt_hi);
    cudaGetSymbolAddress((void**)&cwtl, g_cwt_lo);
    cudaGetSymbolAddress((void**)&xwp,  g_xw);
    cudaGetSymbolAddress((void**)&hdec, g_hdec);
    cudaGetSymbolAddress((void**)&wc,   g_wc);

    cudaFuncSetAttribute(mma_gemm<1,1,1>, cudaFuncAttributeMaxDynamicSharedMemorySize, GEMM_SMEM);
    cudaFuncSetAttribute(mma_gemm<0,0,0>, cudaFuncAttributeMaxDynamicSharedMemorySize, GEMM_SMEM);

    dim3 scan_grid(16, 8);

    // conv: fused im2col+split inside the GEMM A-loader (bias+ReLU, split out)
    wsplit<<<(UU * KC + 255) / 256, 256>>>(cnn_w, cwth, cwtl, KC, UU);
    mma_gemm<1,1,1><<<dim3(UU / 128, MTOT / 128), 256, GEMM_SMEM>>>(
        nullptr, nullptr, x, cwth, cwtl, cnn_b, nullptr, ah, al, MTOT, UU, KC);

    // encoder layer 0
    wsplit<<<(UU * G4) / 256, 256>>>(ew0, wth, wtl, UU, G4);
    mma_gemm<0,0,0><<<dim3(G4 / 128, MTOT / 128), 256, GEMM_SMEM>>>(
        ah, al, nullptr, wth, wtl, eb0, xwp, nullptr, nullptr, MTOT, G4, UU);
    wsplit<<<(UU * G4) / 256, 256>>>(eu0, uth, utl, UU, G4);
    bar_reset<<<1, 32>>>();
    lstm_scan_mma<<<scan_grid, 512>>>(xwp, nullptr, uth, utl, ah, al, nullptr, TT, 0, 1);

    // encoder layer 1
    wsplit<<<(UU * G4) / 256, 256>>>(ew1, wth, wtl, UU, G4);
    mma_gemm<0,0,0><<<dim3(G4 / 128, MTOT / 128), 256, GEMM_SMEM>>>(
        ah, al, nullptr, wth, wtl, eb1, xwp, nullptr, nullptr, MTOT, G4, UU);
    wsplit<<<(UU * G4) / 256, 256>>>(eu1, uth, utl, UU, G4);
    bar_reset<<<1, 32>>>();
    lstm_scan_mma<<<scan_grid, 512>>>(xwp, nullptr, uth, utl, ah, al, nullptr, TT, 0, 1);

    // encoder layer 2 (only final h,c needed)
    wsplit<<<(UU * G4) / 256, 256>>>(ew2, wth, wtl, UU, G4);
    mma_gemm<0,0,0><<<dim3(G4 / 128, MTOT / 128), 256, GEMM_SMEM>>>(
        ah, al, nullptr, wth, wtl, eb2, xwp, nullptr, nullptr, MTOT, G4, UU);
    wsplit<<<(UU * G4) / 256, 256>>>(eu2, uth, utl, UU, G4);
    bar_reset<<<1, 32>>>();
    lstm_scan_mma<<<scan_grid, 512>>>(xwp, nullptr, uth, utl, nullptr, nullptr, nullptr, TT, 0, 0);

    // decoder: z = h @ (cell_w + cell_u) + b, 64 steps from (h,c)
    combine_w_kernel<<<(UU * G4) / 256, 256>>>(cw, cu);
    wsplit<<<(UU * G4) / 256, 256>>>(wc, uth, utl, UU, G4);
    bar_reset<<<1, 32>>>();
    lstm_scan_mma<<<scan_grid, 512>>>(nullptr, cb, uth, utl, nullptr, nullptr, hdec, OUTS, 1, 2);

    // dense head
    dense_kernel<<<(BB * OUTS * OD) / 256, 256>>>(hdec, dw, db, out);
}